// round 12
// baseline (speedup 1.0000x reference)
#include <cuda_runtime.h>
#include <cstdint>

#define N_NODES 100000
#define CH      128
#define N_REL   16
#define N_EDGES 200000
#define NW      17                        /* self + 16 relations */
#define TM      64                        /* tile rows */
#define NT      ((N_NODES + TM - 1) / TM) /* 1563 dst tiles */
#define NBK     (NT * N_REL * 4)          /* 100032 buckets (tile,rel,gwarp) */
#define HS      136                       /* hA row stride (floats) */
#define HSZ     (TM * HS)                 /* 8704 floats per hA buffer */
#define BSU     132                       /* B smem row stride (u32 = f16x2) */
#define BSLOT   (16 * BSU)                /* 2112 u32 per B stage (K=32 packed) */

// smem: hA0 | hA1 (fp32) | B-ring (2 x BSLOT u32)
#define SMF_B    (2 * HSZ)
#define SMEM_FLOATS (SMF_B + 2 * BSLOT)   /* 21632 floats = 86528 B -> 2 CTA/SM */
#define NSTG     (4 * NW)                 /* 68 B k-chunks */

// ---------------- device scratch ----------------
__device__ unsigned      g_emeta[N_REL * N_EDGES];   // src | dl<<17 (sorted by bucket)
__device__ unsigned      g_Bh[NW * 64 * CH];         // fp16x2-packed weights (k-pairs)
__device__ int           g_deg[N_REL * N_NODES];
__device__ float         g_invdeg[N_REL * N_NODES];
__device__ int           g_bcnt[NBK];
__device__ int           g_boff[NBK + 1];
__device__ int           g_bfill[NBK];
__device__ int           g_bsum[128];
__device__ int           g_flags[2];

// pack two f32 -> f16x2 (lo = first arg)
__device__ __forceinline__ unsigned pack_h2(float lo, float hi) {
    unsigned r;
    asm("cvt.rn.f16x2.f32 %0, %1, %2;" : "=r"(r) : "f"(hi), "f"(lo));
    return r;
}

// ---------------- prep0: detect dtypes + zero + pack weights -------------
__global__ void k_prep0(const unsigned* __restrict__ w, const unsigned char* __restrict__ mb,
                        const float* __restrict__ selfw, const float* __restrict__ relw) {
    if (blockIdx.x == 0) {
        __shared__ int s64, s32;
        if (threadIdx.x == 0) { s64 = 0; s32 = 0; }
        __syncthreads();
        if (threadIdx.x < 128) { if (w[2 * threadIdx.x + 1] != 0u) atomicAdd(&s64, 1); }
        if (threadIdx.x < 192) {
            int i = (threadIdx.x / 3) * 4 + 1 + (threadIdx.x % 3);
            if (mb[i] != 0) atomicAdd(&s32, 1);
        }
        __syncthreads();
        if (threadIdx.x == 0) { g_flags[0] = (s64 < 8); g_flags[1] = (s32 < 8); }
    }
    int stride = gridDim.x * blockDim.x;
    int g = blockIdx.x * blockDim.x + threadIdx.x;
    for (int i = g; i < N_REL * N_NODES; i += stride) g_deg[i] = 0;
    for (int i = g; i < NBK; i += stride) g_bcnt[i] = 0;
    // g_Bh[(w*64 + i)*128 + n] = pack(W[2i][n], W[2i+1][n])
    for (int j = g; j < NW * 64 * CH; j += stride) {
        int wi = j / (64 * CH);
        int r  = j % (64 * CH);
        int i2 = r / CH, n = r % CH;
        const float* W = (wi == 0) ? selfw : relw + (size_t)(wi - 1) * CH * CH;
        float v0 = W[(2 * i2) * CH + n];
        float v1 = W[(2 * i2 + 1) * CH + n];
        g_Bh[j] = pack_h2(v0, v1);
    }
}

__device__ __forceinline__ int rd_idx(const void* p, int i) {
    return g_flags[0] ? (int)((const long long*)p)[i] : ((const int*)p)[i];
}
__device__ __forceinline__ int rd_mask(const void* p, int i) {
    return g_flags[1] ? (((const int*)p)[i] != 0) : (int)((const unsigned char*)p)[i];
}

// ---------------- degree + bucket counting ----------------
__global__ void k_deg(const void* __restrict__ idx, const void* __restrict__ mask) {
    int e = blockIdx.x * blockDim.x + threadIdx.x;
    int rel = blockIdx.y;
    if (e >= N_EDGES) return;
    if (!rd_mask(mask, rel * N_EDGES + e)) return;
    int dst = rd_idx(idx, rel * 2 * N_EDGES + N_EDGES + e);
    atomicAdd(&g_deg[rel * N_NODES + dst], 1);
    int key = ((dst >> 6) * N_REL + rel) * 4 + ((dst >> 4) & 3);
    atomicAdd(&g_bcnt[key], 1);
}

__global__ void k_invdeg() {
    int i = blockIdx.x * blockDim.x + threadIdx.x;
    if (i >= N_REL * N_NODES) return;
    int d = g_deg[i];
    g_invdeg[i] = d > 0 ? 1.0f / (float)d : 0.0f;
}

// ---------------- prefix scan ----------------
__global__ void k_scan1() {
    __shared__ int sh[1024];
    int i = blockIdx.x * 1024 + threadIdx.x;
    int v = (i < NBK) ? g_bcnt[i] : 0;
    sh[threadIdx.x] = v;
    __syncthreads();
    for (int off = 1; off < 1024; off <<= 1) {
        int t = (threadIdx.x >= off) ? sh[threadIdx.x - off] : 0;
        __syncthreads();
        sh[threadIdx.x] += t;
        __syncthreads();
    }
    if (i < NBK) g_boff[i] = sh[threadIdx.x] - v;
    if (threadIdx.x == 1023) g_bsum[blockIdx.x] = sh[1023];
}

__global__ void k_scan2(int nb) {
    __shared__ int sh[128];
    int v = (threadIdx.x < nb) ? g_bsum[threadIdx.x] : 0;
    sh[threadIdx.x] = v;
    __syncthreads();
    for (int off = 1; off < 128; off <<= 1) {
        int t = (threadIdx.x >= off) ? sh[threadIdx.x - off] : 0;
        __syncthreads();
        sh[threadIdx.x] += t;
        __syncthreads();
    }
    if (threadIdx.x < nb) g_bsum[threadIdx.x] = sh[threadIdx.x] - v;
    if (threadIdx.x == 127) g_boff[NBK] = sh[127];
}

__global__ void k_scan3() {
    int i = blockIdx.x * 1024 + threadIdx.x;
    if (i >= NBK) return;
    int o = g_boff[i] + g_bsum[blockIdx.x];
    g_boff[i] = o;
    g_bfill[i] = o;
}

// ---------------- fill sorted edge meta ----------------
__global__ void k_fill(const void* __restrict__ idx, const void* __restrict__ mask) {
    int e = blockIdx.x * blockDim.x + threadIdx.x;
    int rel = blockIdx.y;
    if (e >= N_EDGES) return;
    if (!rd_mask(mask, rel * N_EDGES + e)) return;
    int src = rd_idx(idx, rel * 2 * N_EDGES + e);
    int dst = rd_idx(idx, rel * 2 * N_EDGES + N_EDGES + e);
    int key = ((dst >> 6) * N_REL + rel) * 4 + ((dst >> 4) & 3);
    int pos = atomicAdd(&g_bfill[key], 1);
    g_emeta[pos] = (unsigned)src | ((unsigned)(dst & 63) << 17);
}

// ---------------- fused kernel helpers ----------------
__device__ __forceinline__ void cp16s(void* sdst, const void* gsrc) {
    unsigned s = (unsigned)__cvta_generic_to_shared(sdst);
    asm volatile("cp.async.cg.shared.global [%0], [%1], 16;\n" :: "r"(s), "l"(gsrc));
}

// B stage s into ring slot s&1: 16 i-rows x 128 u32, row stride BSU. mma tids 0..127.
__device__ __forceinline__ void cp_stage(unsigned* sBu, int s, int tid) {
    if (s < NSTG) {
        unsigned* dB = sBu + (s & 1) * BSLOT;
        const unsigned* src0 = g_Bh + (size_t)s * 2048;
#pragma unroll
        for (int j = 0; j < 4; j++) {
            int ch = tid + 128 * j;            // 512 chunks of 16B
            int i = ch >> 5, nb = ch & 31;
            cp16s(dB + i * BSU + nb * 4, src0 + i * 128 + nb * 4);
        }
    }
    asm volatile("cp.async.commit_group;\n");   // uniform group count
}

// fp16 m16n8k16 mma over one K=32 chunk; A fp32 in smem (cvt on the fly),
// B pre-packed f16x2 in smem.
__device__ __forceinline__ void mma4(float (*c)[4][4], const float* A, const unsigned* Bu,
                                     int lane) {
#pragma unroll
    for (int kk = 0; kk < 2; kk++) {
        unsigned a[4][4], b[4][2];
        int c0 = kk * 16 + 2 * (lane & 3);
        int r = lane >> 2;
#pragma unroll
        for (int mf = 0; mf < 4; mf++) {
            const float* Ap = A + (mf * 16 + r) * HS + c0;
            float2 v00 = *(const float2*)(Ap);
            float2 v10 = *(const float2*)(Ap + 8 * HS);
            float2 v01 = *(const float2*)(Ap + 8);
            float2 v11 = *(const float2*)(Ap + 8 * HS + 8);
            a[mf][0] = pack_h2(v00.x, v00.y);
            a[mf][1] = pack_h2(v10.x, v10.y);
            a[mf][2] = pack_h2(v01.x, v01.y);
            a[mf][3] = pack_h2(v11.x, v11.y);
        }
        int i0 = 8 * kk + (lane & 3);
#pragma unroll
        for (int nf = 0; nf < 4; nf++) {
            const unsigned* Bp = Bu + i0 * BSU + nf * 8 + (lane >> 2);
            b[nf][0] = Bp[0];
            b[nf][1] = Bp[4 * BSU];
        }
#pragma unroll
        for (int mf = 0; mf < 4; mf++)
#pragma unroll
            for (int nf = 0; nf < 4; nf++)
                asm volatile(
                    "mma.sync.aligned.m16n8k16.row.col.f32.f16.f16.f32 "
                    "{%0,%1,%2,%3},{%4,%5,%6,%7},{%8,%9},{%0,%1,%2,%3};\n"
                    : "+f"(c[mf][nf][0]), "+f"(c[mf][nf][1]),
                      "+f"(c[mf][nf][2]), "+f"(c[mf][nf][3])
                    : "r"(a[mf][0]), "r"(a[mf][1]), "r"(a[mf][2]), "r"(a[mf][3]),
                      "r"(b[nf][0]), "r"(b[nf][1]));
    }
}

// gather warp gwid: rows [gwid*16, gwid*16+16) = sum x[src]*invdeg (R6/R10 code)
__device__ __forceinline__ void gather_rel(const float* __restrict__ x, float* hb,
                                           int tile, int rel, int gwid, int lane) {
    float4 z = make_float4(0.f, 0.f, 0.f, 0.f);
    int r0 = gwid * 16;
#pragma unroll
    for (int r = 0; r < 16; r++)
        ((float4*)(hb + (r0 + r) * HS))[lane] = z;

    int key = (tile * N_REL + rel) * 4 + gwid;
    int beg = g_boff[key], end = g_boff[key + 1];
    const float* vd = g_invdeg + rel * N_NODES + tile * TM;
    for (int base = beg; base < end; base += 32) {
        unsigned m = 0;
        if (base + lane < end) m = g_emeta[base + lane];
        int n = min(32, end - base);
        int j = 0;
        for (; j + 4 <= n; j += 4) {                 // 4 independent 512B loads in flight
            int dl[4], sn[4];
            float sc[4];
            float4 v[4];
#pragma unroll
            for (int t = 0; t < 4; t++) {
                unsigned u = __shfl_sync(0xffffffffu, m, j + t);
                sn[t] = (int)(u & 0x1FFFFu);
                dl[t] = (int)(u >> 17);
            }
#pragma unroll
            for (int t = 0; t < 4; t++) sc[t] = __ldg(vd + dl[t]);
#pragma unroll
            for (int t = 0; t < 4; t++)
                v[t] = __ldg((const float4*)(x + (size_t)sn[t] * CH) + lane);
#pragma unroll
            for (int t = 0; t < 4; t++) {
                float4* hp = (float4*)(hb + dl[t] * HS) + lane;
                float4 hv = *hp;
                hv.x += v[t].x * sc[t]; hv.y += v[t].y * sc[t];
                hv.z += v[t].z * sc[t]; hv.w += v[t].w * sc[t];
                *hp = hv;
            }
        }
        for (; j < n; j++) {
            unsigned u = __shfl_sync(0xffffffffu, m, j);
            int sn = (int)(u & 0x1FFFFu);
            int dl = (int)(u >> 17);
            float s = __ldg(vd + dl);
            float4 v = __ldg((const float4*)(x + (size_t)sn * CH) + lane);
            float4* hp = (float4*)(hb + dl * HS) + lane;
            float4 hv = *hp;
            hv.x += v.x * s; hv.y += v.y * s; hv.z += v.z * s; hv.w += v.w * s;
            *hp = hv;
        }
    }
}

// ---------------- fused: 64-row tiles, warps 0-3 mma, 4-7 gather, 2 CTA/SM
__global__ __launch_bounds__(256, 2) void k_fused(const float* __restrict__ x,
                                                  float* __restrict__ out) {
    extern __shared__ float sm[];
    float* hA = sm;                         // 2 fp32 buffers
    unsigned* sBu = (unsigned*)(sm + SMF_B); // 2-slot packed-f16 ring
    int tid = threadIdx.x, wid = tid >> 5, lane = tid & 31;
    int tile = blockIdx.x, bM = tile * TM;
    bool is_mma = (wid < 4);

    float c[4][4][4];
#pragma unroll
    for (int i = 0; i < 4; i++)
#pragma unroll
        for (int j = 0; j < 4; j++)
#pragma unroll
            for (int k = 0; k < 4; k++) c[i][j][k] = 0.f;

    if (is_mma) {
        cp_stage(sBu, 0, tid);       // preload stage 0
    } else {
        // self tile (weight 0) = x rows -> hA[0]
        int gwid = wid - 4, r0 = gwid * 16;
#pragma unroll
        for (int r = 0; r < 16; r++) {
            int rg = bM + r0 + r;
            float4 v = make_float4(0.f, 0.f, 0.f, 0.f);
            if (rg < N_NODES) v = __ldg((const float4*)(x + (size_t)rg * CH) + lane);
            ((float4*)(hA + (r0 + r) * HS))[lane] = v;
        }
    }
    __syncthreads();   // hA[0] ready

#pragma unroll 1
    for (int w = 0; w < NW; w++) {
        if (is_mma) {
            int wn = wid;                          // 1x4 warp grid over 64x128
            const float* A = hA + (w & 1) * HSZ;
#pragma unroll 1
            for (int kt = 0; kt < 4; kt++) {
                int s = w * 4 + kt;
                asm volatile("cp.async.wait_group 0;\n");         // stage s landed
                asm volatile("bar.sync 1, 128;\n" ::: "memory");  // mma copies/reads done
                cp_stage(sBu, s + 1, tid);         // slot (s+1)&1: readers done at bar
                mma4(c, A + kt * 32, sBu + (s & 1) * BSLOT + wn * 32, lane);
            }
        } else if (w < NW - 1) {
            // build hA[(w+1)&1] for relation w while mma chews on hA[w&1]
            gather_rel(x, hA + ((w + 1) & 1) * HSZ, tile, w, wid - 4, lane);
        }
        __syncthreads();   // weight boundary: next A ready, current A free
    }

    // epilogue (mma warps own the accumulators)
    if (is_mma) {
        int wn = wid;
#pragma unroll
        for (int mf = 0; mf < 4; mf++) {
            int r0 = bM + mf * 16 + (lane >> 2);
#pragma unroll
            for (int nf = 0; nf < 4; nf++) {
                int cc = wn * 32 + nf * 8 + (lane & 3) * 2;
                if (r0 < N_NODES)
                    *(float2*)(out + (size_t)r0 * CH + cc) =
                        make_float2(c[mf][nf][0], c[mf][nf][1]);
                if (r0 + 8 < N_NODES)
                    *(float2*)(out + (size_t)(r0 + 8) * CH + cc) =
                        make_float2(c[mf][nf][2], c[mf][nf][3]);
            }
        }
    }
}

// ---------------- launch ----------------
extern "C" void kernel_launch(void* const* d_in, const int* in_sizes, int n_in,
                              void* d_out, int out_size) {
    const float* x     = (const float*)d_in[0];
    const void*  idx   = d_in[1];
    const void*  mask  = d_in[2];
    const float* selfw = (const float*)d_in[3];
    const float* relw  = (const float*)d_in[4];
    float* out = (float*)d_out;

    static int init = 0;
    size_t smem = SMEM_FLOATS * sizeof(float);   // 86528 B
    if (!init) {
        cudaFuncSetAttribute(k_fused, cudaFuncAttributeMaxDynamicSharedMemorySize, (int)smem);
        init = 1;
    }

    int nb1 = (NBK + 1023) / 1024;   // 98

    k_prep0<<<4096, 256>>>((const unsigned*)idx, (const unsigned char*)mask, selfw, relw);
    k_deg<<<dim3((N_EDGES + 255) / 256, N_REL), 256>>>(idx, mask);
    k_invdeg<<<(N_REL * N_NODES + 255) / 256, 256>>>();
    k_scan1<<<nb1, 1024>>>();
    k_scan2<<<1, 128>>>(nb1);
    k_scan3<<<nb1, 1024>>>();
    k_fill<<<dim3((N_EDGES + 255) / 256, N_REL), 256>>>(idx, mask);
    k_fused<<<NT, 256, smem>>>(x, out);
}